// round 1
// baseline (speedup 1.0000x reference)
#include <cuda_runtime.h>
#include <math.h>

// Problem constants
#define BB 4
#define SS 2048
#define DD 1024
#define HH 16
#define HD 64
#define MTOT (BB*SS)      // 8192
#define NQKV (3*DD)       // 3072
#define NHEADS (BB*HH)    // 64

// Scratch: Q,K,V and attention output in [B,H,S,HD] layout (32MB each)
__device__ float g_Q[(size_t)NHEADS*SS*HD];
__device__ float g_K[(size_t)NHEADS*SS*HD];
__device__ float g_V[(size_t)NHEADS*SS*HD];
__device__ float g_O[(size_t)NHEADS*SS*HD];

// ---------------------------------------------------------------------------
// GEMM 1: qkv = x[8192,1024] @ Wqkv[1024,3072] + bqkv, scattered into Q/K/V
// 128x128 tile, BK=16, 256 threads, 8x8 per thread (split 4+4 layout for
// conflict-free LDS.128: quarter-warp phases read 8 consecutive float4s).
// ---------------------------------------------------------------------------
__global__ void __launch_bounds__(256) gemm_qkv_kernel(
    const float* __restrict__ A, const float* __restrict__ W,
    const float* __restrict__ bias)
{
    const int m0 = blockIdx.y * 128;
    const int n0 = blockIdx.x * 128;

    __shared__ float As[16][132];  // As[k][m]
    __shared__ float Bs[16][132];  // Bs[k][n]

    const int tid  = threadIdx.x;
    const int warp = tid >> 5;
    const int lane = tid & 31;
    const int wm = warp >> 1;         // 0..3 : 32-row block
    const int wn = warp & 1;          // 0..1 : 64-col block
    const int mi = lane >> 3;         // 0..3
    const int ni = lane & 7;          // 0..7
    const int row0 = wm*32 + mi*4;    // rows row0..row0+3 and +16
    const int col0 = wn*64 + ni*4;    // cols col0..col0+3 and +32

    float c[8][8];
    #pragma unroll
    for (int i = 0; i < 8; i++)
        #pragma unroll
        for (int j = 0; j < 8; j++) c[i][j] = 0.0f;

    // bias for this thread's 8 columns
    float4 bias_a = *(const float4*)(bias + n0 + col0);
    float4 bias_b = *(const float4*)(bias + n0 + col0 + 32);

    const int arow  = tid >> 2;        // 0..63 (+64)
    const int acol4 = (tid & 3) * 4;   // 0,4,8,12

    for (int k0 = 0; k0 < DD; k0 += 16) {
        // load A tile (transpose into As[k][m])
        #pragma unroll
        for (int l = 0; l < 2; l++) {
            int r = arow + l*64;
            float4 a4 = *(const float4*)(A + (size_t)(m0 + r)*DD + k0 + acol4);
            As[acol4+0][r] = a4.x;
            As[acol4+1][r] = a4.y;
            As[acol4+2][r] = a4.z;
            As[acol4+3][r] = a4.w;
        }
        // load B tile (natural)
        #pragma unroll
        for (int l = 0; l < 2; l++) {
            int idx = tid + l*256;
            int r  = idx >> 5;
            int cc = (idx & 31) * 4;
            *(float4*)&Bs[r][cc] = *(const float4*)(W + (size_t)(k0 + r)*NQKV + n0 + cc);
        }
        __syncthreads();

        #pragma unroll
        for (int k = 0; k < 16; k++) {
            float a[8], b[8];
            *(float4*)&a[0] = *(float4*)&As[k][row0];
            *(float4*)&a[4] = *(float4*)&As[k][row0 + 16];
            *(float4*)&b[0] = *(float4*)&Bs[k][col0];
            *(float4*)&b[4] = *(float4*)&Bs[k][col0 + 32];
            #pragma unroll
            for (int i = 0; i < 8; i++)
                #pragma unroll
                for (int j = 0; j < 8; j++)
                    c[i][j] = fmaf(a[i], b[j], c[i][j]);
        }
        __syncthreads();
    }

    // Epilogue: scatter into Q/K/V, layout [b,h,s,hd]
    #pragma unroll
    for (int ih = 0; ih < 2; ih++) {
        #pragma unroll
        for (int i = 0; i < 4; i++) {
            int ri = ih*4 + i;
            int m  = m0 + row0 + ih*16 + i;
            int b  = m >> 11;        // /2048
            int s  = m & 2047;
            #pragma unroll
            for (int jh = 0; jh < 2; jh++) {
                int e = n0 + col0 + jh*32;
                float4 v;
                if (jh == 0) {
                    v.x = c[ri][0] + bias_a.x; v.y = c[ri][1] + bias_a.y;
                    v.z = c[ri][2] + bias_a.z; v.w = c[ri][3] + bias_a.w;
                } else {
                    v.x = c[ri][4] + bias_b.x; v.y = c[ri][5] + bias_b.y;
                    v.z = c[ri][6] + bias_b.z; v.w = c[ri][7] + bias_b.w;
                }
                int h     = e / 192;
                int t     = e - h*192;
                int which = t >> 6;
                int hd    = t & 63;
                float* dst = (which == 0) ? g_Q : (which == 1) ? g_K : g_V;
                *(float4*)&dst[(((size_t)b*HH + h)*SS + s)*HD + hd] = v;
            }
        }
    }
}

// ---------------------------------------------------------------------------
// Flash attention: per (b,h), Q tiles of 64 rows, KV tiles of 64.
// 256 threads; thread (r=tid/8, c=tid&7) owns rows {2r,2r+1},
// cols {4c..4c+3} U {32+4c..32+4c+3}. Online softmax; shfl over 8-lane groups.
// ---------------------------------------------------------------------------
#define APAD 68
#define SMEM_ATTN (4 * 64 * APAD * 4)

__global__ void __launch_bounds__(256) attn_kernel()
{
    const int qt = blockIdx.x;   // 0..31
    const int bh = blockIdx.y;   // 0..63

    const float* Q = g_Q + ((size_t)bh*SS + qt*64) * HD;
    const float* K = g_K + (size_t)bh*SS*HD;
    const float* V = g_V + (size_t)bh*SS*HD;
    float*       O = g_O + ((size_t)bh*SS + qt*64) * HD;

    extern __shared__ float sm[];
    float* Qs = sm;                 // [64][APAD]  (natural [i][d], pre-scaled)
    float* Kt = sm + 64*APAD;       // [64][APAD]  (Kt[d][j])
    float* Vs = Kt + 64*APAD;       // [64][APAD]  (natural [k][d])
    float* Ps = Vs + 64*APAD;       // [64][APAD]  (Ps[i][k])

    const int tid = threadIdx.x;
    const int r   = tid >> 3;       // 0..31
    const int cc  = tid & 7;        // 0..7
    const int ra  = 2*r;
    const int rb  = 2*r + 1;
    const int ca  = 4*cc;
    const int cb  = 32 + 4*cc;

    // Load Q tile, pre-scale by 1/sqrt(HD) = 0.125
    #pragma unroll
    for (int l = 0; l < 4; l++) {
        int idx = tid + l*256;
        int row = idx >> 4;
        int d4  = (idx & 15) * 4;
        float4 q4 = *(const float4*)(Q + row*HD + d4);
        q4.x *= 0.125f; q4.y *= 0.125f; q4.z *= 0.125f; q4.w *= 0.125f;
        *(float4*)&Qs[row*APAD + d4] = q4;
    }

    float mrow[2] = {-1e30f, -1e30f};
    float lrow[2] = {0.0f, 0.0f};
    float o[2][8];
    #pragma unroll
    for (int i = 0; i < 2; i++)
        #pragma unroll
        for (int j = 0; j < 8; j++) o[i][j] = 0.0f;

    for (int t = 0; t < SS/64; t++) {
        __syncthreads();  // Kt/Vs reuse barrier (also covers Qs on t=0)

        const float* Kp = K + (size_t)t*64*HD;
        const float* Vp = V + (size_t)t*64*HD;
        #pragma unroll
        for (int l = 0; l < 4; l++) {
            int idx = tid + l*256;
            int row = idx >> 4;
            int d4  = (idx & 15) * 4;
            float4 k4 = *(const float4*)(Kp + row*HD + d4);
            Kt[(d4+0)*APAD + row] = k4.x;
            Kt[(d4+1)*APAD + row] = k4.y;
            Kt[(d4+2)*APAD + row] = k4.z;
            Kt[(d4+3)*APAD + row] = k4.w;
            *(float4*)&Vs[row*APAD + d4] = *(const float4*)(Vp + row*HD + d4);
        }
        __syncthreads();

        // s = (Q*scale) @ K^T
        float s[2][8];
        #pragma unroll
        for (int i = 0; i < 2; i++)
            #pragma unroll
            for (int j = 0; j < 8; j++) s[i][j] = 0.0f;

        #pragma unroll 16
        for (int d = 0; d < 64; d++) {
            float q0 = Qs[ra*APAD + d];
            float q1 = Qs[rb*APAD + d];
            float4 ka = *(float4*)&Kt[d*APAD + ca];
            float4 kb = *(float4*)&Kt[d*APAD + cb];
            s[0][0] = fmaf(q0, ka.x, s[0][0]); s[0][1] = fmaf(q0, ka.y, s[0][1]);
            s[0][2] = fmaf(q0, ka.z, s[0][2]); s[0][3] = fmaf(q0, ka.w, s[0][3]);
            s[0][4] = fmaf(q0, kb.x, s[0][4]); s[0][5] = fmaf(q0, kb.y, s[0][5]);
            s[0][6] = fmaf(q0, kb.z, s[0][6]); s[0][7] = fmaf(q0, kb.w, s[0][7]);
            s[1][0] = fmaf(q1, ka.x, s[1][0]); s[1][1] = fmaf(q1, ka.y, s[1][1]);
            s[1][2] = fmaf(q1, ka.z, s[1][2]); s[1][3] = fmaf(q1, ka.w, s[1][3]);
            s[1][4] = fmaf(q1, kb.x, s[1][4]); s[1][5] = fmaf(q1, kb.y, s[1][5]);
            s[1][6] = fmaf(q1, kb.z, s[1][6]); s[1][7] = fmaf(q1, kb.w, s[1][7]);
        }

        // online softmax update
        float tm[2];
        #pragma unroll
        for (int i = 0; i < 2; i++) {
            float mx = s[i][0];
            #pragma unroll
            for (int j = 1; j < 8; j++) mx = fmaxf(mx, s[i][j]);
            tm[i] = mx;
        }
        #pragma unroll
        for (int off = 1; off < 8; off <<= 1) {
            tm[0] = fmaxf(tm[0], __shfl_xor_sync(0xffffffffu, tm[0], off));
            tm[1] = fmaxf(tm[1], __shfl_xor_sync(0xffffffffu, tm[1], off));
        }
        float mn0 = fmaxf(mrow[0], tm[0]);
        float mn1 = fmaxf(mrow[1], tm[1]);
        float corr0 = __expf(mrow[0] - mn0);
        float corr1 = __expf(mrow[1] - mn1);

        float ps0 = 0.0f, ps1 = 0.0f;
        #pragma unroll
        for (int j = 0; j < 8; j++) {
            s[0][j] = __expf(s[0][j] - mn0); ps0 += s[0][j];
            s[1][j] = __expf(s[1][j] - mn1); ps1 += s[1][j];
        }
        #pragma unroll
        for (int off = 1; off < 8; off <<= 1) {
            ps0 += __shfl_xor_sync(0xffffffffu, ps0, off);
            ps1 += __shfl_xor_sync(0xffffffffu, ps1, off);
        }
        lrow[0] = lrow[0]*corr0 + ps0;
        lrow[1] = lrow[1]*corr1 + ps1;
        #pragma unroll
        for (int j = 0; j < 8; j++) { o[0][j] *= corr0; o[1][j] *= corr1; }
        mrow[0] = mn0; mrow[1] = mn1;

        // write P tile
        *(float4*)&Ps[ra*APAD + ca] = make_float4(s[0][0], s[0][1], s[0][2], s[0][3]);
        *(float4*)&Ps[ra*APAD + cb] = make_float4(s[0][4], s[0][5], s[0][6], s[0][7]);
        *(float4*)&Ps[rb*APAD + ca] = make_float4(s[1][0], s[1][1], s[1][2], s[1][3]);
        *(float4*)&Ps[rb*APAD + cb] = make_float4(s[1][4], s[1][5], s[1][6], s[1][7]);
        __syncthreads();

        // O += P @ V
        #pragma unroll 16
        for (int k = 0; k < 64; k++) {
            float p0 = Ps[ra*APAD + k];
            float p1 = Ps[rb*APAD + k];
            float4 va = *(float4*)&Vs[k*APAD + ca];
            float4 vb = *(float4*)&Vs[k*APAD + cb];
            o[0][0] = fmaf(p0, va.x, o[0][0]); o[0][1] = fmaf(p0, va.y, o[0][1]);
            o[0][2] = fmaf(p0, va.z, o[0][2]); o[0][3] = fmaf(p0, va.w, o[0][3]);
            o[0][4] = fmaf(p0, vb.x, o[0][4]); o[0][5] = fmaf(p0, vb.y, o[0][5]);
            o[0][6] = fmaf(p0, vb.z, o[0][6]); o[0][7] = fmaf(p0, vb.w, o[0][7]);
            o[1][0] = fmaf(p1, va.x, o[1][0]); o[1][1] = fmaf(p1, va.y, o[1][1]);
            o[1][2] = fmaf(p1, va.z, o[1][2]); o[1][3] = fmaf(p1, va.w, o[1][3]);
            o[1][4] = fmaf(p1, vb.x, o[1][4]); o[1][5] = fmaf(p1, vb.y, o[1][5]);
            o[1][6] = fmaf(p1, vb.z, o[1][6]); o[1][7] = fmaf(p1, vb.w, o[1][7]);
        }
    }

    // finalize and write
    float inv0 = 1.0f / lrow[0];
    float inv1 = 1.0f / lrow[1];
    *(float4*)&O[ra*HD + ca] = make_float4(o[0][0]*inv0, o[0][1]*inv0, o[0][2]*inv0, o[0][3]*inv0);
    *(float4*)&O[ra*HD + cb] = make_float4(o[0][4]*inv0, o[0][5]*inv0, o[0][6]*inv0, o[0][7]*inv0);
    *(float4*)&O[rb*HD + ca] = make_float4(o[1][0]*inv1, o[1][1]*inv1, o[1][2]*inv1, o[1][3]*inv1);
    *(float4*)&O[rb*HD + cb] = make_float4(o[1][4]*inv1, o[1][5]*inv1, o[1][6]*inv1, o[1][7]*inv1);
}

// ---------------------------------------------------------------------------
// GEMM 2: out = values[8192,1024] @ Wo[1024,1024] + bo
// Same structure as GEMM 1, plain epilogue. values = g_O flat (matches the
// reference's head-unpermuted reshape).
// ---------------------------------------------------------------------------
__global__ void __launch_bounds__(256) gemm_out_kernel(
    const float* __restrict__ W, const float* __restrict__ bias,
    float* __restrict__ out)
{
    const int m0 = blockIdx.y * 128;
    const int n0 = blockIdx.x * 128;

    __shared__ float As[16][132];
    __shared__ float Bs[16][132];

    const int tid  = threadIdx.x;
    const int warp = tid >> 5;
    const int lane = tid & 31;
    const int wm = warp >> 1;
    const int wn = warp & 1;
    const int mi = lane >> 3;
    const int ni = lane & 7;
    const int row0 = wm*32 + mi*4;
    const int col0 = wn*64 + ni*4;

    float c[8][8];
    #pragma unroll
    for (int i = 0; i < 8; i++)
        #pragma unroll
        for (int j = 0; j < 8; j++) c[i][j] = 0.0f;

    float4 bias_a = *(const float4*)(bias + n0 + col0);
    float4 bias_b = *(const float4*)(bias + n0 + col0 + 32);

    const int arow  = tid >> 2;
    const int acol4 = (tid & 3) * 4;
    const float* A = g_O;

    for (int k0 = 0; k0 < DD; k0 += 16) {
        #pragma unroll
        for (int l = 0; l < 2; l++) {
            int r = arow + l*64;
            float4 a4 = *(const float4*)(A + (size_t)(m0 + r)*DD + k0 + acol4);
            As[acol4+0][r] = a4.x;
            As[acol4+1][r] = a4.y;
            As[acol4+2][r] = a4.z;
            As[acol4+3][r] = a4.w;
        }
        #pragma unroll
        for (int l = 0; l < 2; l++) {
            int idx = tid + l*256;
            int rr  = idx >> 5;
            int ccc = (idx & 31) * 4;
            *(float4*)&Bs[rr][ccc] = *(const float4*)(W + (size_t)(k0 + rr)*DD + n0 + ccc);
        }
        __syncthreads();

        #pragma unroll
        for (int k = 0; k < 16; k++) {
            float a[8], b[8];
            *(float4*)&a[0] = *(float4*)&As[k][row0];
            *(float4*)&a[4] = *(float4*)&As[k][row0 + 16];
            *(float4*)&b[0] = *(float4*)&Bs[k][col0];
            *(float4*)&b[4] = *(float4*)&Bs[k][col0 + 32];
            #pragma unroll
            for (int i = 0; i < 8; i++)
                #pragma unroll
                for (int j = 0; j < 8; j++)
                    c[i][j] = fmaf(a[i], b[j], c[i][j]);
        }
        __syncthreads();
    }

    #pragma unroll
    for (int ih = 0; ih < 2; ih++) {
        #pragma unroll
        for (int i = 0; i < 4; i++) {
            int ri = ih*4 + i;
            int m  = m0 + row0 + ih*16 + i;
            float4 va, vb;
            va.x = c[ri][0] + bias_a.x; va.y = c[ri][1] + bias_a.y;
            va.z = c[ri][2] + bias_a.z; va.w = c[ri][3] + bias_a.w;
            vb.x = c[ri][4] + bias_b.x; vb.y = c[ri][5] + bias_b.y;
            vb.z = c[ri][6] + bias_b.z; vb.w = c[ri][7] + bias_b.w;
            *(float4*)&out[(size_t)m*DD + n0 + col0]      = va;
            *(float4*)&out[(size_t)m*DD + n0 + col0 + 32] = vb;
        }
    }
}

// ---------------------------------------------------------------------------
extern "C" void kernel_launch(void* const* d_in, const int* in_sizes, int n_in,
                              void* d_out, int out_size)
{
    const float* x    = (const float*)d_in[0];
    const float* Wqkv = (const float*)d_in[1];
    const float* bqkv = (const float*)d_in[2];
    const float* Wo   = (const float*)d_in[3];
    const float* bo   = (const float*)d_in[4];
    float* out = (float*)d_out;

    cudaFuncSetAttribute(attn_kernel,
                         cudaFuncAttributeMaxDynamicSharedMemorySize, SMEM_ATTN);

    gemm_qkv_kernel<<<dim3(NQKV/128, MTOT/128), 256>>>(x, Wqkv, bqkv);
    attn_kernel<<<dim3(SS/64, NHEADS), 256, SMEM_ATTN>>>();
    gemm_out_kernel<<<dim3(DD/128, MTOT/128), 256>>>(Wo, bo, out);
}

// round 3
// speedup vs baseline: 2.2175x; 2.2175x over previous
#include <cuda_runtime.h>
#include <cuda_bf16.h>
#include <cstdint>
#include <math.h>

// Problem constants
#define BB 4
#define SS 2048
#define DD 1024
#define HH 16
#define HD 64
#define MTOT (BB*SS)      // 8192
#define NQKV (3*DD)       // 3072
#define NHEADS (BB*HH)    // 64

// Q pre-scale: 1/sqrt(64) * log2(e)  (softmax done in exp2 domain)
#define QSCALE 0.1803368801111204f

// ---------------------------------------------------------------------------
// Scratch (static device globals — allowed)
// ---------------------------------------------------------------------------
__device__ __nv_bfloat16 g_Xh[(size_t)MTOT*DD];
__device__ __nv_bfloat16 g_Xl[(size_t)MTOT*DD];
__device__ __nv_bfloat16 g_WqTh[(size_t)NQKV*DD];
__device__ __nv_bfloat16 g_WqTl[(size_t)NQKV*DD];
__device__ __nv_bfloat16 g_WoTh[(size_t)DD*DD];
__device__ __nv_bfloat16 g_WoTl[(size_t)DD*DD];
__device__ __nv_bfloat16 g_Qh[(size_t)NHEADS*SS*HD];
__device__ __nv_bfloat16 g_Ql[(size_t)NHEADS*SS*HD];
__device__ __nv_bfloat16 g_Kh[(size_t)NHEADS*SS*HD];
__device__ __nv_bfloat16 g_Kl[(size_t)NHEADS*SS*HD];
__device__ __nv_bfloat16 g_Vh[(size_t)NHEADS*SS*HD];
__device__ __nv_bfloat16 g_Vl[(size_t)NHEADS*SS*HD];
__device__ __nv_bfloat16 g_Oh[(size_t)MTOT*DD];
__device__ __nv_bfloat16 g_Ol[(size_t)MTOT*DD];

// ---------------------------------------------------------------------------
// PTX helpers (plain compute_103-compatible: mma.sync / ldmatrix / cp.async)
// ---------------------------------------------------------------------------
__device__ __forceinline__ uint32_t smem_u32(const void* p) {
    uint32_t a;
    asm("{ .reg .u64 t; cvta.to.shared.u64 t, %1; cvt.u32.u64 %0, t; }"
        : "=r"(a) : "l"(p));
    return a;
}
__device__ __forceinline__ void cp16(uint32_t dst, const void* src) {
    asm volatile("cp.async.cg.shared.global [%0], [%1], 16;\n"
                 :: "r"(dst), "l"(src));
}
#define CP_COMMIT() asm volatile("cp.async.commit_group;\n" ::: "memory")
#define CP_WAIT(n)  asm volatile("cp.async.wait_group %0;\n" :: "n"(n) : "memory")

__device__ __forceinline__ void ldsm4(uint32_t* r, uint32_t addr) {
    asm volatile("ldmatrix.sync.aligned.m8n8.x4.shared.b16 {%0,%1,%2,%3}, [%4];\n"
                 : "=r"(r[0]), "=r"(r[1]), "=r"(r[2]), "=r"(r[3]) : "r"(addr));
}
__device__ __forceinline__ void ldsm4t(uint32_t* r, uint32_t addr) {
    asm volatile("ldmatrix.sync.aligned.m8n8.x4.trans.shared.b16 {%0,%1,%2,%3}, [%4];\n"
                 : "=r"(r[0]), "=r"(r[1]), "=r"(r[2]), "=r"(r[3]) : "r"(addr));
}
__device__ __forceinline__ void mma_bf16(float* c, const uint32_t* a,
                                         uint32_t b0, uint32_t b1) {
    asm volatile(
        "mma.sync.aligned.m16n8k16.row.col.f32.bf16.bf16.f32 "
        "{%0,%1,%2,%3}, {%4,%5,%6,%7}, {%8,%9}, {%0,%1,%2,%3};\n"
        : "+f"(c[0]), "+f"(c[1]), "+f"(c[2]), "+f"(c[3])
        : "r"(a[0]), "r"(a[1]), "r"(a[2]), "r"(a[3]), "r"(b0), "r"(b1));
}
__device__ __forceinline__ float ex2(float x) {
    float y;
    asm("ex2.approx.ftz.f32 %0, %1;" : "=f"(y) : "f"(x));
    return y;
}
__device__ __forceinline__ void split2(float x, float y,
                                       __nv_bfloat162& h2, __nv_bfloat162& l2) {
    __nv_bfloat16 hx = __float2bfloat16(x);
    __nv_bfloat16 hy = __float2bfloat16(y);
    h2.x = hx; h2.y = hy;
    l2.x = __float2bfloat16(x - __bfloat162float(hx));
    l2.y = __float2bfloat16(y - __bfloat162float(hy));
}

// ---------------------------------------------------------------------------
// Prep: split x into bf16 hi/lo
// ---------------------------------------------------------------------------
__global__ void __launch_bounds__(256) split_x_kernel(const float* __restrict__ x)
{
    size_t i4 = ((size_t)blockIdx.x * 256 + threadIdx.x) * 4;
    float4 v = *(const float4*)(x + i4);
    __nv_bfloat162 h0, l0, h1, l1;
    split2(v.x, v.y, h0, l0);
    split2(v.z, v.w, h1, l1);
    *(__nv_bfloat162*)(g_Xh + i4)     = h0;
    *(__nv_bfloat162*)(g_Xh + i4 + 2) = h1;
    *(__nv_bfloat162*)(g_Xl + i4)     = l0;
    *(__nv_bfloat162*)(g_Xl + i4 + 2) = l1;
}

// Prep: transpose W [K][N] -> T[n][k] bf16 hi/lo
__global__ void __launch_bounds__(256) transpose_split_kernel(
    const float* __restrict__ W, int K, int N,
    __nv_bfloat16* __restrict__ Th, __nv_bfloat16* __restrict__ Tl)
{
    __shared__ float t[32][33];
    int nb = blockIdx.x * 32, kb = blockIdx.y * 32;
    int tx = threadIdx.x, ty = threadIdx.y;
    #pragma unroll
    for (int j = 0; j < 4; j++)
        t[ty + j*8][tx] = W[(size_t)(kb + ty + j*8) * N + nb + tx];
    __syncthreads();
    #pragma unroll
    for (int j = 0; j < 4; j++) {
        int n = nb + ty + j*8;
        float v = t[tx][ty + j*8];
        __nv_bfloat16 h = __float2bfloat16(v);
        Th[(size_t)n * K + kb + tx] = h;
        Tl[(size_t)n * K + kb + tx] = __float2bfloat16(v - __bfloat162float(h));
    }
}

// ---------------------------------------------------------------------------
// Extended-K bf16 GEMM (3-pass split as K=3072):
//   C[M][N] = sum_p  Ap . Bp^T   with A pattern [h|l|h], B pattern [h|h|l]
// BM=BN=128, BK=32, 256 threads, 8 warps (2m x 4n), 4-stage cp.async.
// mode 0: +bqkv, scale Q cols, split, scatter to g_{Q,K,V}{h,l}
// mode 1: +bo, fp32 store to out
// ---------------------------------------------------------------------------
#define GSTG 10240          // 128 rows * 80B per operand per stage
#define SMEM_GEMM (8*GSTG)  // A:4 stages, B:4 stages

__global__ void __launch_bounds__(256, 1) gemm_ext_kernel(
    const __nv_bfloat16* __restrict__ Ah, const __nv_bfloat16* __restrict__ Al,
    const __nv_bfloat16* __restrict__ Bh, const __nv_bfloat16* __restrict__ Bl,
    const float* __restrict__ bias, float* __restrict__ out, int mode)
{
    extern __shared__ char sm[];
    const uint32_t sb = smem_u32(sm);
    const int tid = threadIdx.x, wid = tid >> 5, lane = tid & 31;
    const int wm = wid >> 2, wn = wid & 3;   // 2 x 4 warp grid
    const int m0 = blockIdx.y * 128, n0 = blockIdx.x * 128;

    const int lrow = tid >> 2;       // 0..63
    const int lq   = tid & 3;        // 16B quad

    float acc[4][4][4];
    #pragma unroll
    for (int i = 0; i < 4; i++)
        #pragma unroll
        for (int j = 0; j < 4; j++)
            #pragma unroll
            for (int e = 0; e < 4; e++) acc[i][j][e] = 0.0f;

    // issue one K-chunk (32 ext-K) into stage c&3
    #define GEMM_ISSUE(c) do {                                                 \
        int _p = (c) >> 5; int _kb = ((c) & 31) * 32;                          \
        const __nv_bfloat16* _Ap = (_p == 1) ? Al : Ah;                        \
        const __nv_bfloat16* _Bp = (_p == 2) ? Bl : Bh;                        \
        uint32_t _da = sb + ((c) & 3) * GSTG;                                  \
        uint32_t _db = sb + 4*GSTG + ((c) & 3) * GSTG;                         \
        cp16(_da + lrow*80 + lq*16,      _Ap + (size_t)(m0+lrow)*DD + _kb + lq*8); \
        cp16(_da + (lrow+64)*80 + lq*16, _Ap + (size_t)(m0+lrow+64)*DD + _kb + lq*8); \
        cp16(_db + lrow*80 + lq*16,      _Bp + (size_t)(n0+lrow)*DD + _kb + lq*8); \
        cp16(_db + (lrow+64)*80 + lq*16, _Bp + (size_t)(n0+lrow+64)*DD + _kb + lq*8); \
    } while (0)

    GEMM_ISSUE(0); CP_COMMIT();
    GEMM_ISSUE(1); CP_COMMIT();
    GEMM_ISSUE(2); CP_COMMIT();

    const int NCH = 96;  // 3072 / 32
    for (int c = 0; c < NCH; c++) {
        CP_WAIT(2);
        __syncthreads();
        if (c + 3 < NCH) GEMM_ISSUE(c + 3);
        CP_COMMIT();

        uint32_t da = sb + (c & 3) * GSTG;
        uint32_t db = sb + 4*GSTG + (c & 3) * GSTG;

        uint32_t bfr[4][4];
        #pragma unroll
        for (int nt = 0; nt < 4; nt++)
            ldsm4(bfr[nt], db + (wn*32 + nt*8 + (lane & 7))*80 + (lane >> 3)*16);

        #pragma unroll
        for (int kk = 0; kk < 2; kk++) {
            uint32_t afr[4][4];
            #pragma unroll
            for (int mt = 0; mt < 4; mt++)
                ldsm4(afr[mt], da + (wm*64 + mt*16 + (lane & 15))*80
                               + kk*32 + (lane >> 4)*16);
            #pragma unroll
            for (int mt = 0; mt < 4; mt++)
                #pragma unroll
                for (int nt = 0; nt < 4; nt++)
                    mma_bf16(acc[mt][nt], afr[mt], bfr[nt][kk*2], bfr[nt][kk*2+1]);
        }
    }

    // ---- epilogue ----
    #pragma unroll
    for (int mt = 0; mt < 4; mt++) {
        #pragma unroll
        for (int rr = 0; rr < 2; rr++) {
            int row = wm*64 + mt*16 + (lane >> 2) + rr*8;
            int m = m0 + row;
            #pragma unroll
            for (int nt = 0; nt < 4; nt++) {
                int col = n0 + wn*32 + nt*8 + 2*(lane & 3);
                float v0 = acc[mt][nt][rr*2]   + bias[col];
                float v1 = acc[mt][nt][rr*2+1] + bias[col+1];
                if (mode == 1) {
                    float2 f2; f2.x = v0; f2.y = v1;
                    *(float2*)&out[(size_t)m*DD + col] = f2;
                } else {
                    int h = col / 192;
                    int t = col - h*192;
                    int which = t >> 6;
                    int hd = t & 63;
                    if (which == 0) { v0 *= QSCALE; v1 *= QSCALE; }
                    __nv_bfloat162 h2, l2;
                    split2(v0, v1, h2, l2);
                    int b = m >> 11, s = m & 2047;
                    size_t off = (((size_t)b*HH + h)*SS + s)*HD + hd;
                    __nv_bfloat16* dh = (which == 0) ? g_Qh : (which == 1) ? g_Kh : g_Vh;
                    __nv_bfloat16* dl = (which == 0) ? g_Ql : (which == 1) ? g_Kl : g_Vl;
                    *(__nv_bfloat162*)(dh + off) = h2;
                    *(__nv_bfloat162*)(dl + off) = l2;
                }
            }
        }
    }
}

// ---------------------------------------------------------------------------
// Flash attention via mma.sync, 3-pass split on QK^T and P.V.
// Q tile 128 rows, KV tile 64. 8 warps: wm=wid>>1 (32 q-rows), wn=wid&1.
// smem rows padded: Q/K/P 400B (192+pad bf16), V 144B (64+pad bf16).
// ---------------------------------------------------------------------------
#define QS_OFF  0
#define KS_OFF  51200                  // Q: 128*400
#define VS_OFF  (KS_OFF + 2*25600)     // K: 2 bufs * 64*400
#define PS_OFF  (VS_OFF + 2*27648)     // V: 2 bufs * 192*144
#define RED_OFF (PS_OFF + 51200)       // P: 128*400
#define SMEM_ATTN (RED_OFF + 2048)     // red: 2*2*128 floats

__global__ void __launch_bounds__(256, 1) attn_kernel()
{
    const int qt = blockIdx.x;   // 0..15
    const int bh = blockIdx.y;   // 0..63
    extern __shared__ char sm[];
    const uint32_t sb = smem_u32(sm);
    const int tid = threadIdx.x, wid = tid >> 5, lane = tid & 31;
    const int wm = wid >> 1, wn = wid & 1;

    const size_t base = (size_t)bh * SS * HD;
    const __nv_bfloat16* Qh = g_Qh + base + (size_t)qt*128*HD;
    const __nv_bfloat16* Ql = g_Ql + base + (size_t)qt*128*HD;
    const __nv_bfloat16* Kh = g_Kh + base;
    const __nv_bfloat16* Kl = g_Kl + base;
    const __nv_bfloat16* Vh = g_Vh + base;
    const __nv_bfloat16* Vl = g_Vl + base;

    // ---- load Q (pattern [h|l|h]) : part of cp.async group 0 ----
    #pragma unroll
    for (int p = 0; p < 3; p++) {
        const __nv_bfloat16* src = (p == 1) ? Ql : Qh;
        #pragma unroll
        for (int j = 0; j < 2; j++) {
            int idx = tid + j*256;          // 512 of 1024 ops here...
            int row = idx >> 3, q = idx & 7;
            cp16(sb + QS_OFF + row*400 + p*128 + q*16, src + (size_t)row*HD + q*8);
            idx += 512;
            row = idx >> 3; q = idx & 7;
            cp16(sb + QS_OFF + row*400 + p*128 + q*16, src + (size_t)row*HD + q*8);
        }
    }

    // K/V tile loader (K pattern [h|h|l] over cols; V pattern [h;h;l] over rows)
    #define LOAD_KV(t, buf) do {                                               \
        int _s0 = (t) * 64;                                                    \
        _Pragma("unroll")                                                      \
        for (int p = 0; p < 3; p++) {                                          \
            const __nv_bfloat16* _Ks = (p == 2) ? Kl : Kh;                     \
            const __nv_bfloat16* _Vs = (p == 2) ? Vl : Vh;                     \
            int _i = tid + p*512;  /* reuse flat mapping per p: 512 ops */     \
            int _row = (tid) >> 3, _q = (tid) & 7;                             \
            cp16(sb + KS_OFF + (buf)*25600 + _row*400 + p*128 + _q*16,         \
                 _Ks + (size_t)(_s0 + _row)*HD + _q*8);                        \
            int _row2 = (tid + 256) >> 3, _q2 = (tid + 256) & 7;               \
            cp16(sb + KS_OFF + (buf)*25600 + _row2*400 + p*128 + _q2*16,       \
                 _Ks + (size_t)(_s0 + _row2)*HD + _q2*8);                      \
            cp16(sb + VS_OFF + (buf)*27648 + (p*64 + _row)*144 + _q*16,        \
                 _Vs + (size_t)(_s0 + _row)*HD + _q*8);                        \
            cp16(sb + VS_OFF + (buf)*27648 + (p*64 + _row2)*144 + _q2*16,      \
                 _Vs + (size_t)(_s0 + _row2)*HD + _q2*8);                      \
            (void)_i;                                                          \
        }                                                                      \
    } while (0)

    LOAD_KV(0, 0);
    CP_COMMIT();

    float oacc[2][4][4];
    #pragma unroll
    for (int i = 0; i < 2; i++)
        #pragma unroll
        for (int j = 0; j < 4; j++)
            #pragma unroll
            for (int e = 0; e < 4; e++) oacc[i][j][e] = 0.0f;
    float mst[2][2], lst[2][2];
    #pragma unroll
    for (int i = 0; i < 2; i++)
        #pragma unroll
        for (int j = 0; j < 2; j++) { mst[i][j] = -1e30f; lst[i][j] = 0.0f; }

    float* redm = (float*)(sm + RED_OFF);   // [2][128]
    float* reds = redm + 256;               // [2][128]
    const int rbase = wm*32 + (lane >> 2);

    for (int t = 0; t < 32; t++) {
        const int buf = t & 1;
        __syncthreads();                       // safe to overwrite buf^1
        if (t + 1 < 32) LOAD_KV(t + 1, buf ^ 1);
        CP_COMMIT();
        CP_WAIT(1);
        __syncthreads();                       // tile t visible to all warps

        // ---- S = Q_ext . K_ext^T (128 x 64, ext K = 192) ----
        float sacc[2][4][4];
        #pragma unroll
        for (int i = 0; i < 2; i++)
            #pragma unroll
            for (int j = 0; j < 4; j++)
                #pragma unroll
                for (int e = 0; e < 4; e++) sacc[i][j][e] = 0.0f;

        const uint32_t kb = sb + KS_OFF + buf*25600;
        #pragma unroll
        for (int kc = 0; kc < 6; kc++) {
            uint32_t bfr[4][4];
            #pragma unroll
            for (int nt = 0; nt < 4; nt++)
                ldsm4(bfr[nt], kb + (wn*32 + nt*8 + (lane & 7))*400
                               + kc*64 + (lane >> 3)*16);
            #pragma unroll
            for (int kk = 0; kk < 2; kk++) {
                uint32_t afr[2][4];
                #pragma unroll
                for (int mt = 0; mt < 2; mt++)
                    ldsm4(afr[mt], sb + QS_OFF + (wm*32 + mt*16 + (lane & 15))*400
                                   + kc*64 + kk*32 + (lane >> 4)*16);
                #pragma unroll
                for (int mt = 0; mt < 2; mt++)
                    #pragma unroll
                    for (int nt = 0; nt < 4; nt++)
                        mma_bf16(sacc[mt][nt], afr[mt], bfr[nt][kk*2], bfr[nt][kk*2+1]);
            }
        }

        // ---- online softmax (exp2 domain) ----
        float wmax[2][2];
        #pragma unroll
        for (int mt = 0; mt < 2; mt++)
            #pragma unroll
            for (int rr = 0; rr < 2; rr++) {
                float mx = sacc[mt][0][rr*2];
                #pragma unroll
                for (int nt = 0; nt < 4; nt++) {
                    mx = fmaxf(mx, sacc[mt][nt][rr*2]);
                    mx = fmaxf(mx, sacc[mt][nt][rr*2+1]);
                }
                mx = fmaxf(mx, __shfl_xor_sync(0xffffffffu, mx, 1));
                mx = fmaxf(mx, __shfl_xor_sync(0xffffffffu, mx, 2));
                wmax[mt][rr] = mx;
                if ((lane & 3) == 0)
                    redm[wn*128 + rbase + mt*16 + rr*8] = mx;
            }
        __syncthreads();

        float alpha[2][2];
        #pragma unroll
        for (int mt = 0; mt < 2; mt++)
            #pragma unroll
            for (int rr = 0; rr < 2; rr++) {
                int row = rbase + mt*16 + rr*8;
                float rm = fmaxf(redm[row], redm[128 + row]);
                float mn = fmaxf(mst[mt][rr], rm);
                alpha[mt][rr] = ex2(mst[mt][rr] - mn);
                mst[mt][rr] = mn;
                float sum = 0.0f;
                #pragma unroll
                for (int nt = 0; nt < 4; nt++) {
                    float p0 = ex2(sacc[mt][nt][rr*2]   - mn);
                    float p1 = ex2(sacc[mt][nt][rr*2+1] - mn);
                    sacc[mt][nt][rr*2] = p0; sacc[mt][nt][rr*2+1] = p1;
                    sum += p0 + p1;
                }
                sum += __shfl_xor_sync(0xffffffffu, sum, 1);
                sum += __shfl_xor_sync(0xffffffffu, sum, 2);
                if ((lane & 3) == 0)
                    reds[wn*128 + row] = sum;
            }

        // write P_ext (pattern [Ph | Pl | Ph]) as bf16
        #pragma unroll
        for (int mt = 0; mt < 2; mt++)
            #pragma unroll
            for (int rr = 0; rr < 2; rr++) {
                int row = rbase + mt*16 + rr*8;
                char* prow = sm + PS_OFF + row*400;
                #pragma unroll
                for (int nt = 0; nt < 4; nt++) {
                    int klc = wn*32 + nt*8 + 2*(lane & 3);
                    __nv_bfloat162 h2, l2;
                    split2(sacc[mt][nt][rr*2], sacc[mt][nt][rr*2+1], h2, l2);
                    *(__nv_bfloat162*)(prow + klc*2)       = h2;
                    *(__nv_bfloat162*)(prow + 128 + klc*2) = l2;
                    *(__nv_bfloat162*)(prow + 256 + klc*2) = h2;
                }
            }
        __syncthreads();

        // l update + O rescale
        #pragma unroll
        for (int mt = 0; mt < 2; mt++)
            #pragma unroll
            for (int rr = 0; rr < 2; rr++) {
                int row = rbase + mt*16 + rr*8;
                lst[mt][rr] = lst[mt][rr]*alpha[mt][rr] + reds[row] + reds[128+row];
                #pragma unroll
                for (int nt = 0; nt < 4; nt++) {
                    oacc[mt][nt][rr*2]   *= alpha[mt][rr];
                    oacc[mt][nt][rr*2+1] *= alpha[mt][rr];
                }
            }

        // ---- O += P_ext . V_ext (ext K = 192 over keys) ----
        const uint32_t vb = sb + VS_OFF + buf*27648;
        #pragma unroll
        for (int k16 = 0; k16 < 12; k16++) {
            uint32_t afr[2][4];
            #pragma unroll
            for (int mt = 0; mt < 2; mt++)
                ldsm4(afr[mt], sb + PS_OFF + (wm*32 + mt*16 + (lane & 15))*400
                               + k16*32 + (lane >> 4)*16);
            uint32_t bfr[2][4];
            #pragma unroll
            for (int ng = 0; ng < 2; ng++)
                ldsm4t(bfr[ng], vb + (k16*16 + (lane & 7) + ((lane >> 3) & 1)*8)*144
                                + (wn*32 + ng*16 + (lane >> 4)*8)*2);
            #pragma unroll
            for (int mt = 0; mt < 2; mt++)
                #pragma unroll
                for (int nt = 0; nt < 4; nt++) {
                    int ng = nt >> 1, nh = nt & 1;
                    mma_bf16(oacc[mt][nt], afr[mt], bfr[ng][nh*2], bfr[ng][nh*2+1]);
                }
        }
    }

    // ---- finalize: O/l, split, store ----
    #pragma unroll
    for (int mt = 0; mt < 2; mt++)
        #pragma unroll
        for (int rr = 0; rr < 2; rr++) {
            float inv = 1.0f / lst[mt][rr];
            int row = rbase + mt*16 + rr*8;
            size_t off0 = base + (size_t)(qt*128 + row)*HD;
            #pragma unroll
            for (int nt = 0; nt < 4; nt++) {
                int hd = wn*32 + nt*8 + 2*(lane & 3);
                __nv_bfloat162 h2, l2;
                split2(oacc[mt][nt][rr*2]*inv, oacc[mt][nt][rr*2+1]*inv, h2, l2);
                *(__nv_bfloat162*)(g_Oh + off0 + hd) = h2;
                *(__nv_bfloat162*)(g_Ol + off0 + hd) = l2;
            }
        }
}

// ---------------------------------------------------------------------------
extern "C" void kernel_launch(void* const* d_in, const int* in_sizes, int n_in,
                              void* d_out, int out_size)
{
    const float* x    = (const float*)d_in[0];
    const float* Wqkv = (const float*)d_in[1];
    const float* bqkv = (const float*)d_in[2];
    const float* Wo   = (const float*)d_in[3];
    const float* bo   = (const float*)d_in[4];
    float* out = (float*)d_out;

    cudaFuncSetAttribute(gemm_ext_kernel,
                         cudaFuncAttributeMaxDynamicSharedMemorySize, SMEM_GEMM);
    cudaFuncSetAttribute(attn_kernel,
                         cudaFuncAttributeMaxDynamicSharedMemorySize, SMEM_ATTN);

    __nv_bfloat16 *Xh, *Xl, *WqTh, *WqTl, *WoTh, *WoTl, *Oh, *Ol;
    cudaGetSymbolAddress((void**)&Xh,   g_Xh);
    cudaGetSymbolAddress((void**)&Xl,   g_Xl);
    cudaGetSymbolAddress((void**)&WqTh, g_WqTh);
    cudaGetSymbolAddress((void**)&WqTl, g_WqTl);
    cudaGetSymbolAddress((void**)&WoTh, g_WoTh);
    cudaGetSymbolAddress((void**)&WoTl, g_WoTl);
    cudaGetSymbolAddress((void**)&Oh,   g_Oh);
    cudaGetSymbolAddress((void**)&Ol,   g_Ol);

    split_x_kernel<<<MTOT*DD/1024, 256>>>(x);
    transpose_split_kernel<<<dim3(NQKV/32, DD/32), dim3(32, 8)>>>(Wqkv, DD, NQKV, WqTh, WqTl);
    transpose_split_kernel<<<dim3(DD/32, DD/32), dim3(32, 8)>>>(Wo, DD, DD, WoTh, WoTl);

    gemm_ext_kernel<<<dim3(NQKV/128, MTOT/128), 256, SMEM_GEMM>>>(
        Xh, Xl, WqTh, WqTl, bqkv, nullptr, 0);

    attn_kernel<<<dim3(SS/128, NHEADS), 256, SMEM_ATTN>>>();

    gemm_ext_kernel<<<dim3(DD/128, MTOT/128), 256, SMEM_GEMM>>>(
        Oh, Ol, WoTh, WoTl, bo, out, 1);
}

// round 5
// speedup vs baseline: 2.8293x; 1.2759x over previous
#include <cuda_runtime.h>
#include <cuda_bf16.h>
#include <cstdint>
#include <math.h>

// Problem constants
#define BB 4
#define SS 2048
#define DD 1024
#define HH 16
#define HD 64
#define MTOT (BB*SS)      // 8192
#define NQKV (3*DD)       // 3072
#define NHEADS (BB*HH)    // 64

// Q pre-scale: 1/sqrt(64) * log2(e)  (softmax done in exp2 domain)
#define QSCALE 0.1803368801111204f

// ---------------------------------------------------------------------------
// Scratch (static device globals — allowed)
// ---------------------------------------------------------------------------
__device__ __nv_bfloat16 g_Xh[(size_t)MTOT*DD];
__device__ __nv_bfloat16 g_Xl[(size_t)MTOT*DD];
__device__ __nv_bfloat16 g_WqTh[(size_t)NQKV*DD];
__device__ __nv_bfloat16 g_WqTl[(size_t)NQKV*DD];
__device__ __nv_bfloat16 g_WoTh[(size_t)DD*DD];
__device__ __nv_bfloat16 g_WoTl[(size_t)DD*DD];
__device__ __nv_bfloat16 g_Qh[(size_t)NHEADS*SS*HD];
__device__ __nv_bfloat16 g_Ql[(size_t)NHEADS*SS*HD];
__device__ __nv_bfloat16 g_Kh[(size_t)NHEADS*SS*HD];
__device__ __nv_bfloat16 g_Kl[(size_t)NHEADS*SS*HD];
__device__ __nv_bfloat16 g_Vh[(size_t)NHEADS*SS*HD];
__device__ __nv_bfloat16 g_Vl[(size_t)NHEADS*SS*HD];
__device__ __nv_bfloat16 g_Oh[(size_t)MTOT*DD];
__device__ __nv_bfloat16 g_Ol[(size_t)MTOT*DD];

// ---------------------------------------------------------------------------
// PTX helpers (plain compute_103-compatible: mma.sync / ldmatrix / cp.async)
// ---------------------------------------------------------------------------
__device__ __forceinline__ uint32_t smem_u32(const void* p) {
    uint32_t a;
    asm("{ .reg .u64 t; cvta.to.shared.u64 t, %1; cvt.u32.u64 %0, t; }"
        : "=r"(a) : "l"(p));
    return a;
}
__device__ __forceinline__ void cp16(uint32_t dst, const void* src) {
    asm volatile("cp.async.cg.shared.global [%0], [%1], 16;\n"
                 :: "r"(dst), "l"(src));
}
#define CP_COMMIT() asm volatile("cp.async.commit_group;\n" ::: "memory")
#define CP_WAIT(n)  asm volatile("cp.async.wait_group %0;\n" :: "n"(n) : "memory")

__device__ __forceinline__ void ldsm4(uint32_t* r, uint32_t addr) {
    asm volatile("ldmatrix.sync.aligned.m8n8.x4.shared.b16 {%0,%1,%2,%3}, [%4];\n"
                 : "=r"(r[0]), "=r"(r[1]), "=r"(r[2]), "=r"(r[3]) : "r"(addr));
}
__device__ __forceinline__ void ldsm4t(uint32_t* r, uint32_t addr) {
    asm volatile("ldmatrix.sync.aligned.m8n8.x4.trans.shared.b16 {%0,%1,%2,%3}, [%4];\n"
                 : "=r"(r[0]), "=r"(r[1]), "=r"(r[2]), "=r"(r[3]) : "r"(addr));
}
__device__ __forceinline__ void mma_bf16(float* c, const uint32_t* a,
                                         uint32_t b0, uint32_t b1) {
    asm volatile(
        "mma.sync.aligned.m16n8k16.row.col.f32.bf16.bf16.f32 "
        "{%0,%1,%2,%3}, {%4,%5,%6,%7}, {%8,%9}, {%0,%1,%2,%3};\n"
        : "+f"(c[0]), "+f"(c[1]), "+f"(c[2]), "+f"(c[3])
        : "r"(a[0]), "r"(a[1]), "r"(a[2]), "r"(a[3]), "r"(b0), "r"(b1));
}
__device__ __forceinline__ float ex2(float x) {
    float y;
    asm("ex2.approx.ftz.f32 %0, %1;" : "=f"(y) : "f"(x));
    return y;
}
__device__ __forceinline__ void split2(float x, float y,
                                       __nv_bfloat162& h2, __nv_bfloat162& l2) {
    __nv_bfloat16 hx = __float2bfloat16(x);
    __nv_bfloat16 hy = __float2bfloat16(y);
    h2.x = hx; h2.y = hy;
    l2.x = __float2bfloat16(x - __bfloat162float(hx));
    l2.y = __float2bfloat16(y - __bfloat162float(hy));
}

// ---------------------------------------------------------------------------
// Prep: split x into bf16 hi/lo
// ---------------------------------------------------------------------------
__global__ void __launch_bounds__(256) split_x_kernel(const float* __restrict__ x)
{
    size_t i4 = ((size_t)blockIdx.x * 256 + threadIdx.x) * 4;
    float4 v = *(const float4*)(x + i4);
    __nv_bfloat162 h0, l0, h1, l1;
    split2(v.x, v.y, h0, l0);
    split2(v.z, v.w, h1, l1);
    *(__nv_bfloat162*)(g_Xh + i4)     = h0;
    *(__nv_bfloat162*)(g_Xh + i4 + 2) = h1;
    *(__nv_bfloat162*)(g_Xl + i4)     = l0;
    *(__nv_bfloat162*)(g_Xl + i4 + 2) = l1;
}

// Prep: transpose W [K][N] -> T[n][k] bf16 hi/lo
__global__ void __launch_bounds__(256) transpose_split_kernel(
    const float* __restrict__ W, int K, int N,
    __nv_bfloat16* __restrict__ Th, __nv_bfloat16* __restrict__ Tl)
{
    __shared__ float t[32][33];
    int nb = blockIdx.x * 32, kb = blockIdx.y * 32;
    int tx = threadIdx.x, ty = threadIdx.y;
    #pragma unroll
    for (int j = 0; j < 4; j++)
        t[ty + j*8][tx] = W[(size_t)(kb + ty + j*8) * N + nb + tx];
    __syncthreads();
    #pragma unroll
    for (int j = 0; j < 4; j++) {
        int n = nb + ty + j*8;
        float v = t[tx][ty + j*8];
        __nv_bfloat16 h = __float2bfloat16(v);
        Th[(size_t)n * K + kb + tx] = h;
        Tl[(size_t)n * K + kb + tx] = __float2bfloat16(v - __bfloat162float(h));
    }
}

// ---------------------------------------------------------------------------
// Extended-K bf16 GEMM (3-pass split as K=3072):
//   C[M][N] = sum_p  Ap . Bp^T   with A pattern [h|l|h], B pattern [h|h|l]
// BM=BN=128, BK=32, 256 threads, 8 warps (2m x 4n), 3-stage cp.async,
// 2 CTAs/SM (launch_bounds reg cap 128, smem 60KB).
// ---------------------------------------------------------------------------
#define GSTG 10240          // 128 rows * 80B per operand per stage
#define SMEM_GEMM (6*GSTG)  // A:3 stages, B:3 stages

__global__ void __launch_bounds__(256, 2) gemm_ext_kernel(
    const __nv_bfloat16* __restrict__ Ah, const __nv_bfloat16* __restrict__ Al,
    const __nv_bfloat16* __restrict__ Bh, const __nv_bfloat16* __restrict__ Bl,
    const float* __restrict__ bias, float* __restrict__ out, int mode)
{
    extern __shared__ char sm[];
    const uint32_t sb = smem_u32(sm);
    const int tid = threadIdx.x, wid = tid >> 5, lane = tid & 31;
    const int wm = wid >> 2, wn = wid & 3;   // 2 x 4 warp grid
    const int m0 = blockIdx.y * 128, n0 = blockIdx.x * 128;

    const int lrow = tid >> 2;       // 0..63
    const int lq   = tid & 3;        // 16B quad

    float acc[4][4][4];
    #pragma unroll
    for (int i = 0; i < 4; i++)
        #pragma unroll
        for (int j = 0; j < 4; j++)
            #pragma unroll
            for (int e = 0; e < 4; e++) acc[i][j][e] = 0.0f;

    // issue one K-chunk (32 ext-K) into stage st (0..2)
    #define GEMM_ISSUE(c, st) do {                                             \
        int _p = (c) >> 5; int _kb = ((c) & 31) * 32;                          \
        const __nv_bfloat16* _Ap = (_p == 1) ? Al : Ah;                        \
        const __nv_bfloat16* _Bp = (_p == 2) ? Bl : Bh;                        \
        uint32_t _da = sb + (st) * GSTG;                                       \
        uint32_t _db = sb + 3*GSTG + (st) * GSTG;                              \
        cp16(_da + lrow*80 + lq*16,      _Ap + (size_t)(m0+lrow)*DD + _kb + lq*8); \
        cp16(_da + (lrow+64)*80 + lq*16, _Ap + (size_t)(m0+lrow+64)*DD + _kb + lq*8); \
        cp16(_db + lrow*80 + lq*16,      _Bp + (size_t)(n0+lrow)*DD + _kb + lq*8); \
        cp16(_db + (lrow+64)*80 + lq*16, _Bp + (size_t)(n0+lrow+64)*DD + _kb + lq*8); \
    } while (0)

    GEMM_ISSUE(0, 0); CP_COMMIT();
    GEMM_ISSUE(1, 1); CP_COMMIT();

    const int NCH = 96;  // 3072 / 32
    int cur = 0;         // stage of chunk c
    for (int c = 0; c < NCH; c++) {
        CP_WAIT(1);
        __syncthreads();
        int nxt = cur + 2 >= 3 ? cur - 1 : cur + 2;
        if (c + 2 < NCH) GEMM_ISSUE(c + 2, nxt);
        CP_COMMIT();

        uint32_t da = sb + cur * GSTG;
        uint32_t db = sb + 3*GSTG + cur * GSTG;

        uint32_t bfr[4][4];
        #pragma unroll
        for (int nt = 0; nt < 4; nt++)
            ldsm4(bfr[nt], db + (wn*32 + nt*8 + (lane & 7))*80 + (lane >> 3)*16);

        #pragma unroll
        for (int kk = 0; kk < 2; kk++) {
            uint32_t afr[4][4];
            #pragma unroll
            for (int mt = 0; mt < 4; mt++)
                ldsm4(afr[mt], da + (wm*64 + mt*16 + (lane & 15))*80
                               + kk*32 + (lane >> 4)*16);
            #pragma unroll
            for (int mt = 0; mt < 4; mt++)
                #pragma unroll
                for (int nt = 0; nt < 4; nt++)
                    mma_bf16(acc[mt][nt], afr[mt], bfr[nt][kk*2], bfr[nt][kk*2+1]);
        }
        cur = cur + 1 >= 3 ? 0 : cur + 1;
    }

    // ---- epilogue ----
    #pragma unroll
    for (int mt = 0; mt < 4; mt++) {
        #pragma unroll
        for (int rr = 0; rr < 2; rr++) {
            int row = wm*64 + mt*16 + (lane >> 2) + rr*8;
            int m = m0 + row;
            #pragma unroll
            for (int nt = 0; nt < 4; nt++) {
                int col = n0 + wn*32 + nt*8 + 2*(lane & 3);
                float v0 = acc[mt][nt][rr*2]   + bias[col];
                float v1 = acc[mt][nt][rr*2+1] + bias[col+1];
                if (mode == 1) {
                    float2 f2; f2.x = v0; f2.y = v1;
                    *(float2*)&out[(size_t)m*DD + col] = f2;
                } else {
                    int h = col / 192;
                    int t = col - h*192;
                    int which = t >> 6;
                    int hd = t & 63;
                    if (which == 0) { v0 *= QSCALE; v1 *= QSCALE; }
                    __nv_bfloat162 h2, l2;
                    split2(v0, v1, h2, l2);
                    int b = m >> 11, s = m & 2047;
                    size_t off = (((size_t)b*HH + h)*SS + s)*HD + hd;
                    __nv_bfloat16* dh = (which == 0) ? g_Qh : (which == 1) ? g_Kh : g_Vh;
                    __nv_bfloat16* dl = (which == 0) ? g_Ql : (which == 1) ? g_Kl : g_Vl;
                    *(__nv_bfloat162*)(dh + off) = h2;
                    *(__nv_bfloat162*)(dl + off) = l2;
                }
            }
        }
    }
}

// ---------------------------------------------------------------------------
// Flash attention via mma.sync, 3-pass split, physical hi/lo dedup:
// smem stores [Qh|Ql], [Kh|Kl] (272B pitch), [Vh;Vl] (144B pitch, 128 rows),
// [Ph|Pl] (272B pitch); the 3 logical passes index-map onto these.
// Q tile 64 rows, KV tile 64 keys. 8 warps: wm=wid>>1 (16 q-rows), wn=wid&1.
// 2 CTAs/SM (105KB smem).
// ---------------------------------------------------------------------------
#define QPITCH 272
#define VPITCH 144
#define QS_OFF 0
#define KS_OFF 17408                 // Q: 64*272
#define KBUF   17408                 // K buf: 64*272
#define VS_OFF (KS_OFF + 2*KBUF)     // 52224
#define VBUF   18432                 // V buf: 128*144
#define PS_OFF (VS_OFF + 2*VBUF)     // 89088
#define RED_OFF (PS_OFF + 17408)     // 106496
#define SMEM_ATTN (RED_OFF + 1024)   // 107520

__global__ void __launch_bounds__(256, 2) attn_kernel()
{
    const int qt = blockIdx.x;   // 0..31
    const int bh = blockIdx.y;   // 0..63
    extern __shared__ char sm[];
    const uint32_t sb = smem_u32(sm);
    const int tid = threadIdx.x, wid = tid >> 5, lane = tid & 31;
    const int wm = wid >> 1, wn = wid & 1;

    const size_t base = (size_t)bh * SS * HD;
    const __nv_bfloat16* Qh = g_Qh + base + (size_t)qt*64*HD;
    const __nv_bfloat16* Ql = g_Ql + base + (size_t)qt*64*HD;
    const __nv_bfloat16* Kh = g_Kh + base;
    const __nv_bfloat16* Kl = g_Kl + base;
    const __nv_bfloat16* Vh = g_Vh + base;
    const __nv_bfloat16* Vl = g_Vl + base;

    // ---- load Q: phys [Qh(128B) | Ql(128B)] per row ----
    #pragma unroll
    for (int j = 0; j < 4; j++) {
        int idx = tid + j*256;
        int row = idx >> 4, q = idx & 15;
        if (q < 8)
            cp16(sb + QS_OFF + row*QPITCH + q*16, Qh + (size_t)row*HD + q*8);
        else
            cp16(sb + QS_OFF + row*QPITCH + 128 + (q-8)*16, Ql + (size_t)row*HD + (q-8)*8);
    }

    // K/V tile loader: K phys [Kh|Kl] 272B pitch; V phys [Vh rows 0-63; Vl rows 64-127]
    #define LOAD_KV(t, buf) do {                                               \
        int _s0 = (t) * 64;                                                    \
        _Pragma("unroll")                                                      \
        for (int j = 0; j < 4; j++) {                                          \
            int _idx = tid + j*256;                                            \
            int _row = _idx >> 4, _q = _idx & 15;                              \
            if (_q < 8)                                                        \
                cp16(sb + KS_OFF + (buf)*KBUF + _row*QPITCH + _q*16,           \
                     Kh + (size_t)(_s0 + _row)*HD + _q*8);                     \
            else                                                               \
                cp16(sb + KS_OFF + (buf)*KBUF + _row*QPITCH + 128 + (_q-8)*16, \
                     Kl + (size_t)(_s0 + _row)*HD + (_q-8)*8);                 \
        }                                                                      \
        _Pragma("unroll")                                                      \
        for (int j = 0; j < 4; j++) {                                          \
            int _idx = tid + j*256;                                            \
            int _vr = _idx >> 3, _q = _idx & 7;                                \
            const __nv_bfloat16* _src = (_vr < 64)                             \
                ? Vh + (size_t)(_s0 + _vr)*HD + _q*8                           \
                : Vl + (size_t)(_s0 + _vr - 64)*HD + _q*8;                     \
            cp16(sb + VS_OFF + (buf)*VBUF + _vr*VPITCH + _q*16, _src);         \
        }                                                                      \
    } while (0)

    LOAD_KV(0, 0);
    CP_COMMIT();

    float oacc[4][4];
    #pragma unroll
    for (int j = 0; j < 4; j++)
        #pragma unroll
        for (int e = 0; e < 4; e++) oacc[j][e] = 0.0f;
    float mst[2] = {-1e30f, -1e30f};
    float lst[2] = {0.0f, 0.0f};

    float* redm = (float*)(sm + RED_OFF);   // [2][64]
    float* reds = redm + 128;               // [2][64]
    const int rbase = wm*16 + (lane >> 2);

    // pass index maps (byte offsets within 272B rows); each kc = 32 ext-K
    const int qoff_tab[6] = {0, 64, 128, 192, 0, 64};     // Q: [h|l|h]
    const int koff_tab[6] = {0, 64, 0, 64, 128, 192};     // K: [h|h|l]

    for (int t = 0; t < 32; t++) {
        const int buf = t & 1;
        __syncthreads();                       // all warps done with buf^1
        if (t + 1 < 32) LOAD_KV(t + 1, buf ^ 1);
        CP_COMMIT();
        CP_WAIT(1);
        __syncthreads();                       // tile t visible to all warps

        // ---- S = Q_ext . K_ext^T (64 x 64, ext K = 192) ----
        float sacc[4][4];
        #pragma unroll
        for (int j = 0; j < 4; j++)
            #pragma unroll
            for (int e = 0; e < 4; e++) sacc[j][e] = 0.0f;

        const uint32_t kb = sb + KS_OFF + buf*KBUF;
        #pragma unroll
        for (int kc = 0; kc < 6; kc++) {
            uint32_t bfr[4][4];
            #pragma unroll
            for (int nt = 0; nt < 4; nt++)
                ldsm4(bfr[nt], kb + (wn*32 + nt*8 + (lane & 7))*QPITCH
                               + koff_tab[kc] + (lane >> 3)*16);
            #pragma unroll
            for (int kk = 0; kk < 2; kk++) {
                uint32_t afr[4];
                ldsm4(afr, sb + QS_OFF + (wm*16 + (lane & 15))*QPITCH
                           + qoff_tab[kc] + kk*32 + (lane >> 4)*16);
                #pragma unroll
                for (int nt = 0; nt < 4; nt++)
                    mma_bf16(sacc[nt], afr, bfr[nt][kk*2], bfr[nt][kk*2+1]);
            }
        }

        // ---- online softmax (exp2 domain) ----
        #pragma unroll
        for (int rr = 0; rr < 2; rr++) {
            float mx = sacc[0][rr*2];
            #pragma unroll
            for (int nt = 0; nt < 4; nt++) {
                mx = fmaxf(mx, sacc[nt][rr*2]);
                mx = fmaxf(mx, sacc[nt][rr*2+1]);
            }
            mx = fmaxf(mx, __shfl_xor_sync(0xffffffffu, mx, 1));
            mx = fmaxf(mx, __shfl_xor_sync(0xffffffffu, mx, 2));
            if ((lane & 3) == 0)
                redm[wn*64 + rbase + rr*8] = mx;
        }
        __syncthreads();

        float alpha[2];
        #pragma unroll
        for (int rr = 0; rr < 2; rr++) {
            int row = rbase + rr*8;
            float rm = fmaxf(redm[row], redm[64 + row]);
            float mn = fmaxf(mst[rr], rm);
            alpha[rr] = ex2(mst[rr] - mn);
            mst[rr] = mn;
            float sum = 0.0f;
            #pragma unroll
            for (int nt = 0; nt < 4; nt++) {
                float p0 = ex2(sacc[nt][rr*2]   - mn);
                float p1 = ex2(sacc[nt][rr*2+1] - mn);
                sacc[nt][rr*2] = p0; sacc[nt][rr*2+1] = p1;
                sum += p0 + p1;
            }
            sum += __shfl_xor_sync(0xffffffffu, sum, 1);
            sum += __shfl_xor_sync(0xffffffffu, sum, 2);
            if ((lane & 3) == 0)
                reds[wn*64 + row] = sum;
        }

        // write P phys [Ph(128B) | Pl(128B)]
        #pragma unroll
        for (int rr = 0; rr < 2; rr++) {
            int row = rbase + rr*8;
            char* prow = sm + PS_OFF + row*QPITCH;
            #pragma unroll
            for (int nt = 0; nt < 4; nt++) {
                int klc = wn*32 + nt*8 + 2*(lane & 3);
                __nv_bfloat162 h2, l2;
                split2(sacc[nt][rr*2], sacc[nt][rr*2+1], h2, l2);
                *(__nv_bfloat162*)(prow + klc*2)       = h2;
                *(__nv_bfloat162*)(prow + 128 + klc*2) = l2;
            }
        }
        __syncthreads();

        // l update + O rescale
        #pragma unroll
        for (int rr = 0; rr < 2; rr++) {
            int row = rbase + rr*8;
            lst[rr] = lst[rr]*alpha[rr] + reds[row] + reds[64+row];
            #pragma unroll
            for (int nt = 0; nt < 4; nt++) {
                oacc[nt][rr*2]   *= alpha[rr];
                oacc[nt][rr*2+1] *= alpha[rr];
            }
        }

        // ---- O += P_ext . V_ext (ext K = 192 over keys) ----
        // passes: k16 0-3: Ph.Vh | 4-7: Pl.Vh | 8-11: Ph.Vl
        const uint32_t vb = sb + VS_OFF + buf*VBUF;
        #pragma unroll
        for (int k16 = 0; k16 < 12; k16++) {
            int poff  = (k16 < 4) ? k16*32 : (k16 < 8) ? 128 + (k16-4)*32 : (k16-8)*32;
            int vbase = (k16 < 4) ? k16*16 : (k16 < 8) ? (k16-4)*16 : 64 + (k16-8)*16;
            uint32_t afr[4];
            ldsm4(afr, sb + PS_OFF + (wm*16 + (lane & 15))*QPITCH
                       + poff + (lane >> 4)*16);
            uint32_t bfr[2][4];
            #pragma unroll
            for (int ng = 0; ng < 2; ng++)
                ldsm4t(bfr[ng], vb + (vbase + (lane & 7) + ((lane >> 3) & 1)*8)*VPITCH
                                + (wn*32 + ng*16 + (lane >> 4)*8)*2);
            #pragma unroll
            for (int nt = 0; nt < 4; nt++) {
                int ng = nt >> 1, nh = nt & 1;
                mma_bf16(oacc[nt], afr, bfr[ng][nh*2], bfr[ng][nh*2+1]);
            }
        }
    }

    // ---- finalize: O/l, split, store ----
    #pragma unroll
    for (int rr = 0; rr < 2; rr++) {
        float inv = 1.0f / lst[rr];
        int row = rbase + rr*8;
        size_t off0 = base + (size_t)(qt*64 + row)*HD;
        #pragma unroll
        for (int nt = 0; nt < 4; nt++) {
            int hd = wn*32 + nt*8 + 2*(lane & 3);
            __nv_bfloat162 h2, l2;
            split2(oacc[nt][rr*2]*inv, oacc[nt][rr*2+1]*inv, h2, l2);
            *(__nv_bfloat162*)(g_Oh + off0 + hd) = h2;
            *(__nv_bfloat162*)(g_Ol + off0 + hd) = l2;
        }
    }
}

// ---------------------------------------------------------------------------
extern "C" void kernel_launch(void* const* d_in, const int* in_sizes, int n_in,
                              void* d_out, int out_size)
{
    const float* x    = (const float*)d_in[0];
    const float* Wqkv = (const float*)d_in[1];
    const float* bqkv = (const float*)d_in[2];
    const float* Wo   = (const float*)d_in[3];
    const float* bo   = (const float*)d_in[4];
    float* out = (float*)d_out;

    cudaFuncSetAttribute(gemm_ext_kernel,
                         cudaFuncAttributeMaxDynamicSharedMemorySize, SMEM_GEMM);
    cudaFuncSetAttribute(attn_kernel,
                         cudaFuncAttributeMaxDynamicSharedMemorySize, SMEM_ATTN);

    __nv_bfloat16 *Xh, *Xl, *WqTh, *WqTl, *WoTh, *WoTl, *Oh, *Ol;
    cudaGetSymbolAddress((void**)&Xh,   g_Xh);
    cudaGetSymbolAddress((void**)&Xl,   g_Xl);
    cudaGetSymbolAddress((void**)&WqTh, g_WqTh);
    cudaGetSymbolAddress((void**)&WqTl, g_WqTl);
    cudaGetSymbolAddress((void**)&WoTh, g_WoTh);
    cudaGetSymbolAddress((void**)&WoTl, g_WoTl);
    cudaGetSymbolAddress((void**)&Oh,   g_Oh);
    cudaGetSymbolAddress((void**)&Ol,   g_Ol);

    split_x_kernel<<<MTOT*DD/1024, 256>>>(x);
    transpose_split_kernel<<<dim3(NQKV/32, DD/32), dim3(32, 8)>>>(Wqkv, DD, NQKV, WqTh, WqTl);
    transpose_split_kernel<<<dim3(DD/32, DD/32), dim3(32, 8)>>>(Wo, DD, DD, WoTh, WoTl);

    gemm_ext_kernel<<<dim3(NQKV/128, MTOT/128), 256, SMEM_GEMM>>>(
        Xh, Xl, WqTh, WqTl, bqkv, nullptr, 0);

    attn_kernel<<<dim3(SS/64, NHEADS), 256, SMEM_ATTN>>>();

    gemm_ext_kernel<<<dim3(DD/128, MTOT/128), 256, SMEM_GEMM>>>(
        Oh, Ol, WoTh, WoTl, bo, out, 1);
}

// round 6
// speedup vs baseline: 2.8485x; 1.0068x over previous
#include <cuda_runtime.h>
#include <cuda_bf16.h>
#include <cstdint>
#include <math.h>

// Problem constants
#define BB 4
#define SS 2048
#define DD 1024
#define HH 16
#define HD 64
#define MTOT (BB*SS)      // 8192
#define NQKV (3*DD)       // 3072
#define NHEADS (BB*HH)    // 64

// Q pre-scale: 1/sqrt(64) * log2(e)  (softmax done in exp2 domain)
#define QSCALE 0.1803368801111204f

// ---------------------------------------------------------------------------
// Scratch (static device globals — allowed)
// ---------------------------------------------------------------------------
__device__ __nv_bfloat16 g_Xh[(size_t)MTOT*DD];
__device__ __nv_bfloat16 g_Xl[(size_t)MTOT*DD];
__device__ __nv_bfloat16 g_WqTh[(size_t)NQKV*DD];
__device__ __nv_bfloat16 g_WqTl[(size_t)NQKV*DD];
__device__ __nv_bfloat16 g_WoTh[(size_t)DD*DD];
__device__ __nv_bfloat16 g_WoTl[(size_t)DD*DD];
__device__ __nv_bfloat16 g_Qh[(size_t)NHEADS*SS*HD];
__device__ __nv_bfloat16 g_Ql[(size_t)NHEADS*SS*HD];
__device__ __nv_bfloat16 g_Kh[(size_t)NHEADS*SS*HD];
__device__ __nv_bfloat16 g_Kl[(size_t)NHEADS*SS*HD];
__device__ __nv_bfloat16 g_Vh[(size_t)NHEADS*SS*HD];
__device__ __nv_bfloat16 g_Vl[(size_t)NHEADS*SS*HD];
__device__ __nv_bfloat16 g_Oh[(size_t)MTOT*DD];
__device__ __nv_bfloat16 g_Ol[(size_t)MTOT*DD];

// ---------------------------------------------------------------------------
// PTX helpers (plain compute_103-compatible: mma.sync / ldmatrix / cp.async)
// ---------------------------------------------------------------------------
__device__ __forceinline__ uint32_t smem_u32(const void* p) {
    uint32_t a;
    asm("{ .reg .u64 t; cvta.to.shared.u64 t, %1; cvt.u32.u64 %0, t; }"
        : "=r"(a) : "l"(p));
    return a;
}
__device__ __forceinline__ void cp16(uint32_t dst, const void* src) {
    asm volatile("cp.async.cg.shared.global [%0], [%1], 16;\n"
                 :: "r"(dst), "l"(src));
}
#define CP_COMMIT() asm volatile("cp.async.commit_group;\n" ::: "memory")
#define CP_WAIT(n)  asm volatile("cp.async.wait_group %0;\n" :: "n"(n) : "memory")

__device__ __forceinline__ void ldsm4(uint32_t* r, uint32_t addr) {
    asm volatile("ldmatrix.sync.aligned.m8n8.x4.shared.b16 {%0,%1,%2,%3}, [%4];\n"
                 : "=r"(r[0]), "=r"(r[1]), "=r"(r[2]), "=r"(r[3]) : "r"(addr));
}
__device__ __forceinline__ void ldsm4t(uint32_t* r, uint32_t addr) {
    asm volatile("ldmatrix.sync.aligned.m8n8.x4.trans.shared.b16 {%0,%1,%2,%3}, [%4];\n"
                 : "=r"(r[0]), "=r"(r[1]), "=r"(r[2]), "=r"(r[3]) : "r"(addr));
}
__device__ __forceinline__ void mma_bf16(float* c, const uint32_t* a,
                                         uint32_t b0, uint32_t b1) {
    asm volatile(
        "mma.sync.aligned.m16n8k16.row.col.f32.bf16.bf16.f32 "
        "{%0,%1,%2,%3}, {%4,%5,%6,%7}, {%8,%9}, {%0,%1,%2,%3};\n"
        : "+f"(c[0]), "+f"(c[1]), "+f"(c[2]), "+f"(c[3])
        : "r"(a[0]), "r"(a[1]), "r"(a[2]), "r"(a[3]), "r"(b0), "r"(b1));
}
__device__ __forceinline__ float ex2(float x) {
    float y;
    asm("ex2.approx.ftz.f32 %0, %1;" : "=f"(y) : "f"(x));
    return y;
}
__device__ __forceinline__ void split2(float x, float y,
                                       __nv_bfloat162& h2, __nv_bfloat162& l2) {
    __nv_bfloat16 hx = __float2bfloat16(x);
    __nv_bfloat16 hy = __float2bfloat16(y);
    h2.x = hx; h2.y = hy;
    l2.x = __float2bfloat16(x - __bfloat162float(hx));
    l2.y = __float2bfloat16(y - __bfloat162float(hy));
}

// ---------------------------------------------------------------------------
// Prep: split x into bf16 hi/lo
// ---------------------------------------------------------------------------
__global__ void __launch_bounds__(256) split_x_kernel(const float* __restrict__ x)
{
    size_t i4 = ((size_t)blockIdx.x * 256 + threadIdx.x) * 4;
    float4 v = *(const float4*)(x + i4);
    __nv_bfloat162 h0, l0, h1, l1;
    split2(v.x, v.y, h0, l0);
    split2(v.z, v.w, h1, l1);
    *(__nv_bfloat162*)(g_Xh + i4)     = h0;
    *(__nv_bfloat162*)(g_Xh + i4 + 2) = h1;
    *(__nv_bfloat162*)(g_Xl + i4)     = l0;
    *(__nv_bfloat162*)(g_Xl + i4 + 2) = l1;
}

// Prep: transpose W [K][N] -> T[n][k] bf16 hi/lo
__global__ void __launch_bounds__(256) transpose_split_kernel(
    const float* __restrict__ W, int K, int N,
    __nv_bfloat16* __restrict__ Th, __nv_bfloat16* __restrict__ Tl)
{
    __shared__ float t[32][33];
    int nb = blockIdx.x * 32, kb = blockIdx.y * 32;
    int tx = threadIdx.x, ty = threadIdx.y;
    #pragma unroll
    for (int j = 0; j < 4; j++)
        t[ty + j*8][tx] = W[(size_t)(kb + ty + j*8) * N + nb + tx];
    __syncthreads();
    #pragma unroll
    for (int j = 0; j < 4; j++) {
        int n = nb + ty + j*8;
        float v = t[tx][ty + j*8];
        __nv_bfloat16 h = __float2bfloat16(v);
        Th[(size_t)n * K + kb + tx] = h;
        Tl[(size_t)n * K + kb + tx] = __float2bfloat16(v - __bfloat162float(h));
    }
}

// ---------------------------------------------------------------------------
// Extended-K bf16 GEMM (3-pass split as K=3072):
//   C[M][N] = sum_p  Ap . Bp^T   with A pattern [h|l|h], B pattern [h|h|l]
// BM=BN=128, BK=64 per stage, 256 threads, 8 warps (2m x 4n),
// 3-stage cp.async (110.6KB smem), 2 CTAs/SM. 48 barriers total.
// ---------------------------------------------------------------------------
#define GPITCH 144
#define GSTG (128*GPITCH)   // 18432 per operand per stage
#define SMEM_GEMM (6*GSTG)  // 110592

__global__ void __launch_bounds__(256, 2) gemm_ext_kernel(
    const __nv_bfloat16* __restrict__ Ah, const __nv_bfloat16* __restrict__ Al,
    const __nv_bfloat16* __restrict__ Bh, const __nv_bfloat16* __restrict__ Bl,
    const float* __restrict__ bias, float* __restrict__ out, int mode)
{
    extern __shared__ char sm[];
    const uint32_t sb = smem_u32(sm);
    const int tid = threadIdx.x, wid = tid >> 5, lane = tid & 31;
    const int wm = wid >> 2, wn = wid & 3;   // 2 x 4 warp grid
    const int m0 = blockIdx.y * 128, n0 = blockIdx.x * 128;

    float acc[4][4][4];
    #pragma unroll
    for (int i = 0; i < 4; i++)
        #pragma unroll
        for (int j = 0; j < 4; j++)
            #pragma unroll
            for (int e = 0; e < 4; e++) acc[i][j][e] = 0.0f;

    // issue one 64-K chunk into stage st (0..2): 4 A + 4 B cp16 per thread
    #define GEMM_ISSUE(c, st) do {                                             \
        int _p = (c) >> 4; int _kb = ((c) & 15) * 64;                          \
        const __nv_bfloat16* _Ap = (_p == 1) ? Al : Ah;                        \
        const __nv_bfloat16* _Bp = (_p == 2) ? Bl : Bh;                        \
        uint32_t _da = sb + (st) * GSTG;                                       \
        uint32_t _db = sb + 3*GSTG + (st) * GSTG;                              \
        _Pragma("unroll")                                                      \
        for (int _j = 0; _j < 4; _j++) {                                       \
            int _idx = tid + _j*256;                                           \
            int _row = _idx >> 3, _q = _idx & 7;                               \
            cp16(_da + _row*GPITCH + _q*16,                                    \
                 _Ap + (size_t)(m0+_row)*DD + _kb + _q*8);                     \
            cp16(_db + _row*GPITCH + _q*16,                                    \
                 _Bp + (size_t)(n0+_row)*DD + _kb + _q*8);                     \
        }                                                                      \
    } while (0)

    GEMM_ISSUE(0, 0); CP_COMMIT();
    GEMM_ISSUE(1, 1); CP_COMMIT();

    const int NCH = 48;  // 3072 / 64
    int cur = 0;         // stage of chunk c
    for (int c = 0; c < NCH; c++) {
        CP_WAIT(1);
        __syncthreads();
        int nxt = cur + 2 >= 3 ? cur - 1 : cur + 2;
        if (c + 2 < NCH) GEMM_ISSUE(c + 2, nxt);
        CP_COMMIT();

        uint32_t da = sb + cur * GSTG;
        uint32_t db = sb + 3*GSTG + cur * GSTG;

        #pragma unroll
        for (int kc2 = 0; kc2 < 2; kc2++) {   // two 32-K halves
            uint32_t bfr[4][4];
            #pragma unroll
            for (int nt = 0; nt < 4; nt++)
                ldsm4(bfr[nt], db + (wn*32 + nt*8 + (lane & 7))*GPITCH
                               + kc2*64 + (lane >> 3)*16);
            #pragma unroll
            for (int kk = 0; kk < 2; kk++) {
                uint32_t afr[4][4];
                #pragma unroll
                for (int mt = 0; mt < 4; mt++)
                    ldsm4(afr[mt], da + (wm*64 + mt*16 + (lane & 15))*GPITCH
                                   + kc2*64 + kk*32 + (lane >> 4)*16);
                #pragma unroll
                for (int mt = 0; mt < 4; mt++)
                    #pragma unroll
                    for (int nt = 0; nt < 4; nt++)
                        mma_bf16(acc[mt][nt], afr[mt], bfr[nt][kk*2], bfr[nt][kk*2+1]);
            }
        }
        cur = cur + 1 >= 3 ? 0 : cur + 1;
    }

    // ---- epilogue ----
    #pragma unroll
    for (int mt = 0; mt < 4; mt++) {
        #pragma unroll
        for (int rr = 0; rr < 2; rr++) {
            int row = wm*64 + mt*16 + (lane >> 2) + rr*8;
            int m = m0 + row;
            #pragma unroll
            for (int nt = 0; nt < 4; nt++) {
                int col = n0 + wn*32 + nt*8 + 2*(lane & 3);
                float v0 = acc[mt][nt][rr*2]   + bias[col];
                float v1 = acc[mt][nt][rr*2+1] + bias[col+1];
                if (mode == 1) {
                    float2 f2; f2.x = v0; f2.y = v1;
                    *(float2*)&out[(size_t)m*DD + col] = f2;
                } else {
                    int h = col / 192;
                    int t = col - h*192;
                    int which = t >> 6;
                    int hd = t & 63;
                    if (which == 0) { v0 *= QSCALE; v1 *= QSCALE; }
                    __nv_bfloat162 h2, l2;
                    split2(v0, v1, h2, l2);
                    int b = m >> 11, s = m & 2047;
                    size_t off = (((size_t)b*HH + h)*SS + s)*HD + hd;
                    __nv_bfloat16* dh = (which == 0) ? g_Qh : (which == 1) ? g_Kh : g_Vh;
                    __nv_bfloat16* dl = (which == 0) ? g_Ql : (which == 1) ? g_Kl : g_Vl;
                    *(__nv_bfloat162*)(dh + off) = h2;
                    *(__nv_bfloat162*)(dl + off) = l2;
                }
            }
        }
    }
}

// ---------------------------------------------------------------------------
// Flash attention via mma.sync, 3-pass split, physical hi/lo dedup:
// smem stores [Qh|Ql], [Kh|Kl] (272B pitch), [Vh;Vl] (144B pitch, 128 rows),
// [Ph|Pl] (272B pitch); the 3 logical passes index-map onto these.
// Q tile 64 rows, KV tile 64 keys. 8 warps: wm=wid>>1 (16 q-rows), wn=wid&1.
// 2 CTAs/SM. 3 barriers per KV tile (CP_WAIT(0) full-drain top barrier).
// ---------------------------------------------------------------------------
#define QPITCH 272
#define VPITCH 144
#define QS_OFF 0
#define KS_OFF 17408                 // Q: 64*272
#define KBUF   17408                 // K buf: 64*272
#define VS_OFF (KS_OFF + 2*KBUF)     // 52224
#define VBUF   18432                 // V buf: 128*144
#define PS_OFF (VS_OFF + 2*VBUF)     // 89088
#define RED_OFF (PS_OFF + 17408)     // 106496
#define SMEM_ATTN (RED_OFF + 1024)   // 107520

__global__ void __launch_bounds__(256, 2) attn_kernel()
{
    const int qt = blockIdx.x;   // 0..31
    const int bh = blockIdx.y;   // 0..63
    extern __shared__ char sm[];
    const uint32_t sb = smem_u32(sm);
    const int tid = threadIdx.x, wid = tid >> 5, lane = tid & 31;
    const int wm = wid >> 1, wn = wid & 1;

    const size_t base = (size_t)bh * SS * HD;
    const __nv_bfloat16* Qh = g_Qh + base + (size_t)qt*64*HD;
    const __nv_bfloat16* Ql = g_Ql + base + (size_t)qt*64*HD;
    const __nv_bfloat16* Kh = g_Kh + base;
    const __nv_bfloat16* Kl = g_Kl + base;
    const __nv_bfloat16* Vh = g_Vh + base;
    const __nv_bfloat16* Vl = g_Vl + base;

    // ---- load Q: phys [Qh(128B) | Ql(128B)] per row ----
    #pragma unroll
    for (int j = 0; j < 4; j++) {
        int idx = tid + j*256;
        int row = idx >> 4, q = idx & 15;
        if (q < 8)
            cp16(sb + QS_OFF + row*QPITCH + q*16, Qh + (size_t)row*HD + q*8);
        else
            cp16(sb + QS_OFF + row*QPITCH + 128 + (q-8)*16, Ql + (size_t)row*HD + (q-8)*8);
    }

    // K/V tile loader: K phys [Kh|Kl] 272B pitch; V phys [Vh rows 0-63; Vl rows 64-127]
    #define LOAD_KV(t, buf) do {                                               \
        int _s0 = (t) * 64;                                                    \
        _Pragma("unroll")                                                      \
        for (int j = 0; j < 4; j++) {                                          \
            int _idx = tid + j*256;                                            \
            int _row = _idx >> 4, _q = _idx & 15;                              \
            if (_q < 8)                                                        \
                cp16(sb + KS_OFF + (buf)*KBUF + _row*QPITCH + _q*16,           \
                     Kh + (size_t)(_s0 + _row)*HD + _q*8);                     \
            else                                                               \
                cp16(sb + KS_OFF + (buf)*KBUF + _row*QPITCH + 128 + (_q-8)*16, \
                     Kl + (size_t)(_s0 + _row)*HD + (_q-8)*8);                 \
        }                                                                      \
        _Pragma("unroll")                                                      \
        for (int j = 0; j < 4; j++) {                                          \
            int _idx = tid + j*256;                                            \
            int _vr = _idx >> 3, _q = _idx & 7;                                \
            const __nv_bfloat16* _src = (_vr < 64)                             \
                ? Vh + (size_t)(_s0 + _vr)*HD + _q*8                           \
                : Vl + (size_t)(_s0 + _vr - 64)*HD + _q*8;                     \
            cp16(sb + VS_OFF + (buf)*VBUF + _vr*VPITCH + _q*16, _src);         \
        }                                                                      \
    } while (0)

    LOAD_KV(0, 0);
    CP_COMMIT();

    float oacc[4][4];
    #pragma unroll
    for (int j = 0; j < 4; j++)
        #pragma unroll
        for (int e = 0; e < 4; e++) oacc[j][e] = 0.0f;
    float mst[2] = {-1e30f, -1e30f};
    float lst[2] = {0.0f, 0.0f};

    float* redm = (float*)(sm + RED_OFF);   // [2][64]
    float* reds = redm + 128;               // [2][64]
    const int rbase = wm*16 + (lane >> 2);

    // pass index maps (byte offsets within 272B rows); each kc = 32 ext-K
    const int qoff_tab[6] = {0, 64, 128, 192, 0, 64};     // Q: [h|l|h]
    const int koff_tab[6] = {0, 64, 0, 64, 128, 192};     // K: [h|h|l]

    for (int t = 0; t < 32; t++) {
        const int buf = t & 1;
        CP_WAIT(0);                            // tile t fully arrived
        __syncthreads();                       // + all warps past PV(t-1)
        if (t + 1 < 32) LOAD_KV(t + 1, buf ^ 1);
        CP_COMMIT();

        // ---- S = Q_ext . K_ext^T (64 x 64, ext K = 192) ----
        float sacc[4][4];
        #pragma unroll
        for (int j = 0; j < 4; j++)
            #pragma unroll
            for (int e = 0; e < 4; e++) sacc[j][e] = 0.0f;

        const uint32_t kb = sb + KS_OFF + buf*KBUF;
        #pragma unroll
        for (int kc = 0; kc < 6; kc++) {
            uint32_t bfr[4][4];
            #pragma unroll
            for (int nt = 0; nt < 4; nt++)
                ldsm4(bfr[nt], kb + (wn*32 + nt*8 + (lane & 7))*QPITCH
                               + koff_tab[kc] + (lane >> 3)*16);
            #pragma unroll
            for (int kk = 0; kk < 2; kk++) {
                uint32_t afr[4];
                ldsm4(afr, sb + QS_OFF + (wm*16 + (lane & 15))*QPITCH
                           + qoff_tab[kc] + kk*32 + (lane >> 4)*16);
                #pragma unroll
                for (int nt = 0; nt < 4; nt++)
                    mma_bf16(sacc[nt], afr, bfr[nt][kk*2], bfr[nt][kk*2+1]);
            }
        }

        // ---- online softmax (exp2 domain) ----
        #pragma unroll
        for (int rr = 0; rr < 2; rr++) {
            float mx = sacc[0][rr*2];
            #pragma unroll
            for (int nt = 0; nt < 4; nt++) {
                mx = fmaxf(mx, sacc[nt][rr*2]);
                mx = fmaxf(mx, sacc[nt][rr*2+1]);
            }
            mx = fmaxf(mx, __shfl_xor_sync(0xffffffffu, mx, 1));
            mx = fmaxf(mx, __shfl_xor_sync(0xffffffffu, mx, 2));
            if ((lane & 3) == 0)
                redm[wn*64 + rbase + rr*8] = mx;
        }
        __syncthreads();

        float alpha[2];
        #pragma unroll
        for (int rr = 0; rr < 2; rr++) {
            int row = rbase + rr*8;
            float rm = fmaxf(redm[row], redm[64 + row]);
            float mn = fmaxf(mst[rr], rm);
            alpha[rr] = ex2(mst[rr] - mn);
            mst[rr] = mn;
            float sum = 0.0f;
            #pragma unroll
            for (int nt = 0; nt < 4; nt++) {
                float p0 = ex2(sacc[nt][rr*2]   - mn);
                float p1 = ex2(sacc[nt][rr*2+1] - mn);
                sacc[nt][rr*2] = p0; sacc[nt][rr*2+1] = p1;
                sum += p0 + p1;
            }
            sum += __shfl_xor_sync(0xffffffffu, sum, 1);
            sum += __shfl_xor_sync(0xffffffffu, sum, 2);
            if ((lane & 3) == 0)
                reds[wn*64 + row] = sum;
        }

        // write P phys [Ph(128B) | Pl(128B)]
        #pragma unroll
        for (int rr = 0; rr < 2; rr++) {
            int row = rbase + rr*8;
            char* prow = sm + PS_OFF + row*QPITCH;
            #pragma unroll
            for (int nt = 0; nt < 4; nt++) {
                int klc = wn*32 + nt*8 + 2*(lane & 3);
                __nv_bfloat162 h2, l2;
                split2(sacc[nt][rr*2], sacc[nt][rr*2+1], h2, l2);
                *(__nv_bfloat162*)(prow + klc*2)       = h2;
                *(__nv_bfloat162*)(prow + 128 + klc*2) = l2;
            }
        }
        __syncthreads();

        // l update + O rescale
        #pragma unroll
        for (int rr = 0; rr < 2; rr++) {
            int row = rbase + rr*8;
            lst[rr] = lst[rr]*alpha[rr] + reds[row] + reds[64+row];
            #pragma unroll
            for (int nt = 0; nt < 4; nt++) {
                oacc[nt][rr*2]   *= alpha[rr];
                oacc[nt][rr*2+1] *= alpha[rr];
            }
        }

        // ---- O += P_ext . V_ext (ext K = 192 over keys) ----
        // passes: k16 0-3: Ph.Vh | 4-7: Pl.Vh | 8-11: Ph.Vl
        const uint32_t vb = sb + VS_OFF + buf*VBUF;
        #pragma unroll
        for (int k16 = 0; k16 < 12; k16++) {
            int poff  = (k16 < 4) ? k16*32 : (k16 < 8) ? 128 + (k16-4)*32 : (k16-8)*32;
            int vbase = (k16 < 4) ? k16*16 : (k16 < 8) ? (k16-4)*16 : 64 + (k16-8)*16;
            uint32_t afr[4];
            ldsm4(afr, sb + PS_OFF + (wm*16 + (lane & 15))*QPITCH
                       + poff + (lane >> 4)*16);
            uint32_t bfr[2][4];
            #pragma unroll
            for (int ng = 0; ng < 2; ng++)
                ldsm4t(bfr[ng], vb + (vbase + (lane & 7) + ((lane >> 3) & 1)*8)*VPITCH
                                + (wn*32 + ng*16 + (lane >> 4)*8)*2);
            #pragma unroll
            for (int nt = 0; nt < 4; nt++) {
                int ng = nt >> 1, nh = nt & 1;
                mma_bf16(oacc[nt], afr, bfr[ng][nh*2], bfr[ng][nh*2+1]);
            }
        }
    }

    // ---- finalize: O/l, split, store ----
    #pragma unroll
    for (int rr = 0; rr < 2; rr++) {
        float inv = 1.0f / lst[rr];
        int row = rbase + rr*8;
        size_t off0 = base + (size_t)(qt*64 + row)*HD;
        #pragma unroll
        for (int nt = 0; nt < 4; nt++) {
            int hd = wn*32 + nt*8 + 2*(lane & 3);
            __nv_bfloat162 h2, l2;
            split2(oacc[nt][rr*2]*inv, oacc[nt][rr*2+1]*inv, h2, l2);
            *(__nv_bfloat162*)(g_Oh + off0 + hd) = h2;
            *(__nv_bfloat162*)(g_Ol + off0 + hd) = l2;
        }
    }
}

// ---------------------------------------------------------------------------
extern "C" void kernel_launch(void* const* d_in, const int* in_sizes, int n_in,
                              void* d_out, int out_size)
{
    const float* x    = (const float*)d_in[0];
    const float* Wqkv = (const float*)d_in[1];
    const float* bqkv = (const float*)d_in[2];
    const float* Wo   = (const float*)d_in[3];
    const float* bo   = (const float*)d_in[4];
    float* out = (float*)d_out;

    cudaFuncSetAttribute(gemm_ext_kernel,
                         cudaFuncAttributeMaxDynamicSharedMemorySize, SMEM_GEMM);
    cudaFuncSetAttribute(attn_kernel,
                         cudaFuncAttributeMaxDynamicSharedMemorySize, SMEM_ATTN);

    __nv_bfloat16 *Xh, *Xl, *WqTh, *WqTl, *WoTh, *WoTl, *Oh, *Ol;
    cudaGetSymbolAddress((void**)&Xh,   g_Xh);
    cudaGetSymbolAddress((void**)&Xl,   g_Xl);
    cudaGetSymbolAddress((void**)&WqTh, g_WqTh);
    cudaGetSymbolAddress((void**)&WqTl, g_WqTl);
    cudaGetSymbolAddress((void**)&WoTh, g_WoTh);
    cudaGetSymbolAddress((void**)&WoTl, g_WoTl);
    cudaGetSymbolAddress((void**)&Oh,   g_Oh);
    cudaGetSymbolAddress((void**)&Ol,   g_Ol);

    split_x_kernel<<<MTOT*DD/1024, 256>>>(x);
    transpose_split_kernel<<<dim3(NQKV/32, DD/32), dim3(32, 8)>>>(Wqkv, DD, NQKV, WqTh, WqTl);
    transpose_split_kernel<<<dim3(DD/32, DD/32), dim3(32, 8)>>>(Wo, DD, DD, WoTh, WoTl);

    gemm_ext_kernel<<<dim3(NQKV/128, MTOT/128), 256, SMEM_GEMM>>>(
        Xh, Xl, WqTh, WqTl, bqkv, nullptr, 0);

    attn_kernel<<<dim3(SS/64, NHEADS), 256, SMEM_ATTN>>>();

    gemm_ext_kernel<<<dim3(DD/128, MTOT/128), 256, SMEM_GEMM>>>(
        Oh, Ol, WoTh, WoTl, bo, out, 1);
}